// round 4
// baseline (speedup 1.0000x reference)
#include <cuda_runtime.h>
#include <cstdint>

// patches: [N=128, C=4, P=32, P, P] f32
// vol:     [B=2,  C=4, H=128, H, H] f32
// centers: [N, 3] i32 ; lower = center - 16 (in [0, 96])
// out = 0.5 * (vol + sum of covering patches)   -- gather, one pass, no atomics.

#define C_DIM 4
#define P_DIM 32
#define H_DIM 128

// per-patch strides in float4 units
#define PATCH_F4   32768u   // C*P^3/4
#define PC_F4      8192u    // P^3/4      (channel stride)
#define PI_F4      256u     // P^2/4      (i stride)
#define PJ_F4      8u       // P/4        (j stride)

__global__ void __launch_bounds__(256)
pi_fused_kernel(const float4* __restrict__ patches4,
                const float4* __restrict__ vol4,
                const int*    __restrict__ centers,
                float4*       __restrict__ out4)
{
    __shared__ int s_lo0[64], s_lo1[64], s_lo2[64];

    const unsigned w    = blockIdx.x * 8u + (threadIdx.x >> 5);
    const unsigned lane = threadIdx.x & 31u;
    const unsigned b  = w >> 12;          // 4096 warps per batch
    const unsigned r  = w & 4095u;
    const unsigned x  = r >> 5;           // 128 x values
    const unsigned y0 = (r & 31u) << 2;   // 32 y-groups of 4

    // stage this batch's 64 patch lower bounds into smem
    if (threadIdx.x < 64u) {
        unsigned n = b * 64u + threadIdx.x;
        s_lo0[threadIdx.x] = centers[n * 3 + 0] - (P_DIM / 2);
        s_lo1[threadIdx.x] = centers[n * 3 + 1] - (P_DIM / 2);
        s_lo2[threadIdx.x] = centers[n * 3 + 2] - (P_DIM / 2);
    }
    __syncthreads();

    float4 acc[C_DIM][4];
    #pragma unroll
    for (int c = 0; c < C_DIM; c++)
        #pragma unroll
        for (int yy = 0; yy < 4; yy++)
            acc[c][yy] = make_float4(0.f, 0.f, 0.f, 0.f);

    const float4 Z = make_float4(0.f, 0.f, 0.f, 0.f);
    const float4* pb = patches4 + (size_t)b * 64u * PATCH_F4;

    for (int p = 0; p < 64; p++) {
        unsigned dx = (unsigned)((int)x - s_lo0[p]);
        if (dx >= 32u) continue;                 // warp-uniform
        const int lo1 = s_lo1[p];
        const int lo2 = s_lo2[p];
        const int m   = (int)lane - (lo2 >> 2);  // aligned patch-quad index
        const unsigned s = (unsigned)lo2 & 3u;   // warp-uniform shift
        const bool vL = (unsigned)(m - 1) < 8u;
        const bool vR = (unsigned)m < 8u;
        const float4* prow0 = pb + (size_t)p * PATCH_F4 + dx * PI_F4;

        switch (s) {
        case 0u:
            #pragma unroll
            for (int yy = 0; yy < 4; yy++) {
                unsigned dy = (unsigned)((int)(y0 + yy) - lo1);
                if (dy < 32u) {
                    #pragma unroll
                    for (int c = 0; c < C_DIM; c++) {
                        const float4* pr = prow0 + c * PC_F4 + dy * PJ_F4;
                        float4 qR = vR ? __ldg(pr + m) : Z;
                        acc[c][yy].x += qR.x; acc[c][yy].y += qR.y;
                        acc[c][yy].z += qR.z; acc[c][yy].w += qR.w;
                    }
                }
            }
            break;
        case 1u:
            #pragma unroll
            for (int yy = 0; yy < 4; yy++) {
                unsigned dy = (unsigned)((int)(y0 + yy) - lo1);
                if (dy < 32u) {
                    #pragma unroll
                    for (int c = 0; c < C_DIM; c++) {
                        const float4* pr = prow0 + c * PC_F4 + dy * PJ_F4;
                        float4 qL = vL ? __ldg(pr + (m - 1)) : Z;
                        float4 qR = vR ? __ldg(pr + m)       : Z;
                        acc[c][yy].x += qL.w; acc[c][yy].y += qR.x;
                        acc[c][yy].z += qR.y; acc[c][yy].w += qR.z;
                    }
                }
            }
            break;
        case 2u:
            #pragma unroll
            for (int yy = 0; yy < 4; yy++) {
                unsigned dy = (unsigned)((int)(y0 + yy) - lo1);
                if (dy < 32u) {
                    #pragma unroll
                    for (int c = 0; c < C_DIM; c++) {
                        const float4* pr = prow0 + c * PC_F4 + dy * PJ_F4;
                        float4 qL = vL ? __ldg(pr + (m - 1)) : Z;
                        float4 qR = vR ? __ldg(pr + m)       : Z;
                        acc[c][yy].x += qL.z; acc[c][yy].y += qL.w;
                        acc[c][yy].z += qR.x; acc[c][yy].w += qR.y;
                    }
                }
            }
            break;
        default:
            #pragma unroll
            for (int yy = 0; yy < 4; yy++) {
                unsigned dy = (unsigned)((int)(y0 + yy) - lo1);
                if (dy < 32u) {
                    #pragma unroll
                    for (int c = 0; c < C_DIM; c++) {
                        const float4* pr = prow0 + c * PC_F4 + dy * PJ_F4;
                        float4 qL = vL ? __ldg(pr + (m - 1)) : Z;
                        float4 qR = vR ? __ldg(pr + m)       : Z;
                        acc[c][yy].x += qL.y; acc[c][yy].y += qL.z;
                        acc[c][yy].z += qL.w; acc[c][yy].w += qR.x;
                    }
                }
            }
            break;
        }
    }

    // epilogue: out = 0.5*(vol + acc), each element written exactly once
    #pragma unroll
    for (int c = 0; c < C_DIM; c++) {
        #pragma unroll
        for (int yy = 0; yy < 4; yy++) {
            size_t o = ((((size_t)(b * C_DIM + c) * H_DIM) + x) * H_DIM + (y0 + yy))
                       * (H_DIM / 4) + lane;
            float4 v = vol4[o];
            float4 rr;
            rr.x = (v.x + acc[c][yy].x) * 0.5f;
            rr.y = (v.y + acc[c][yy].y) * 0.5f;
            rr.z = (v.z + acc[c][yy].z) * 0.5f;
            rr.w = (v.w + acc[c][yy].w) * 0.5f;
            out4[o] = rr;
        }
    }
}

extern "C" void kernel_launch(void* const* d_in, const int* in_sizes, int n_in,
                              void* d_out, int out_size) {
    const float4* patches = (const float4*)d_in[0];
    const float4* vol     = (const float4*)d_in[1];
    const int*    centers = (const int*)d_in[2];
    float4*       out     = (float4*)d_out;

    // 8192 warps total (2 batches x 128 x x 32 y-groups), 8 warps per block
    pi_fused_kernel<<<1024, 256>>>(patches, vol, centers, out);
}

// round 5
// speedup vs baseline: 1.7205x; 1.7205x over previous
#include <cuda_runtime.h>
#include <cstdint>

// patches: [N=128, C=4, P=32, P, P] f32
// vol:     [B=2,  C=4, H=128, H, H] f32
// centers: [N, 3] i32 ; lower = center - 16 (in [0, 96])
// out = 0.5 * (vol + sum of covering patches)   -- gather, one pass, no atomics.

#define C_DIM 4
#define P_DIM 32
#define H_DIM 128

// per-patch strides in float4 units
#define PATCH_F4   32768u   // C*P^3/4
#define PC_F4      8192u    // P^3/4   (channel stride)
#define PI_F4      256u     // P^2/4   (i stride)
#define PJ_F4      8u       // P/4     (j stride)

// One warp per (b, x, y) d-line: 2*128*128 = 32768 warps. Lane = d-quad (0..31).
__global__ void __launch_bounds__(256)
pi_fused_kernel(const float4* __restrict__ patches4,
                const float4* __restrict__ vol4,
                const int*    __restrict__ centers,
                float4*       __restrict__ out4)
{
    __shared__ int s_lo0[64], s_lo1[64], s_lo2[64];

    const unsigned w    = blockIdx.x * 8u + (threadIdx.x >> 5);
    const unsigned lane = threadIdx.x & 31u;
    const unsigned b = w >> 14;           // 16384 warps per batch
    const unsigned r = w & 16383u;
    const unsigned x = r >> 7;            // 0..127
    const unsigned y = r & 127u;          // 0..127

    if (threadIdx.x < 64u) {
        unsigned n = b * 64u + threadIdx.x;
        s_lo0[threadIdx.x] = centers[n * 3 + 0] - (P_DIM / 2);
        s_lo1[threadIdx.x] = centers[n * 3 + 1] - (P_DIM / 2);
        s_lo2[threadIdx.x] = centers[n * 3 + 2] - (P_DIM / 2);
    }
    __syncthreads();

    float4 acc0 = make_float4(0.f,0.f,0.f,0.f);
    float4 acc1 = make_float4(0.f,0.f,0.f,0.f);
    float4 acc2 = make_float4(0.f,0.f,0.f,0.f);
    float4 acc3 = make_float4(0.f,0.f,0.f,0.f);

    const float4 Z = make_float4(0.f,0.f,0.f,0.f);
    const float4* pb = patches4 + (size_t)b * 64u * PATCH_F4;

    #define ACCUM_CASE(EX0,EY0,EZ0,EW0)                                        \
        {                                                                       \
            const float4* pr0 = prow + 0u * PC_F4;                              \
            const float4* pr1 = prow + 1u * PC_F4;                              \
            const float4* pr2 = prow + 2u * PC_F4;                              \
            const float4* pr3 = prow + 3u * PC_F4;                              \
            float4 L0 = vL ? __ldg(pr0 + (m-1)) : Z;                            \
            float4 R0 = vR ? __ldg(pr0 + m)     : Z;                            \
            float4 L1 = vL ? __ldg(pr1 + (m-1)) : Z;                            \
            float4 R1 = vR ? __ldg(pr1 + m)     : Z;                            \
            float4 L2 = vL ? __ldg(pr2 + (m-1)) : Z;                            \
            float4 R2 = vR ? __ldg(pr2 + m)     : Z;                            \
            float4 L3 = vL ? __ldg(pr3 + (m-1)) : Z;                            \
            float4 R3 = vR ? __ldg(pr3 + m)     : Z;                            \
            acc0.x += EX0(L0,R0); acc0.y += EY0(L0,R0);                         \
            acc0.z += EZ0(L0,R0); acc0.w += EW0(L0,R0);                         \
            acc1.x += EX0(L1,R1); acc1.y += EY0(L1,R1);                         \
            acc1.z += EZ0(L1,R1); acc1.w += EW0(L1,R1);                         \
            acc2.x += EX0(L2,R2); acc2.y += EY0(L2,R2);                         \
            acc2.z += EZ0(L2,R2); acc2.w += EW0(L2,R2);                         \
            acc3.x += EX0(L3,R3); acc3.y += EY0(L3,R3);                         \
            acc3.z += EZ0(L3,R3); acc3.w += EW0(L3,R3);                         \
        }

    #define SEL_RX(L,R) (R.x)
    #define SEL_RY(L,R) (R.y)
    #define SEL_RZ(L,R) (R.z)
    #define SEL_RW(L,R) (R.w)
    #define SEL_LY(L,R) (L.y)
    #define SEL_LZ(L,R) (L.z)
    #define SEL_LW(L,R) (L.w)

    for (int p = 0; p < 64; p++) {
        unsigned dx = (unsigned)((int)x - s_lo0[p]);
        if (dx >= 32u) continue;                 // warp-uniform
        unsigned dy = (unsigned)((int)y - s_lo1[p]);
        if (dy >= 32u) continue;                 // warp-uniform
        const int lo2 = s_lo2[p];
        const int m   = (int)lane - (lo2 >> 2);  // aligned patch-quad index
        const unsigned s = (unsigned)lo2 & 3u;   // warp-uniform shift
        const bool vL = (unsigned)(m - 1) < 8u;
        const bool vR = (unsigned)m < 8u;
        const float4* prow = pb + (size_t)p * PATCH_F4 + dx * PI_F4 + dy * PJ_F4;

        switch (s) {                              // warp-uniform
        case 0u:  ACCUM_CASE(SEL_RX, SEL_RY, SEL_RZ, SEL_RW) break;
        case 1u:  ACCUM_CASE(SEL_LW, SEL_RX, SEL_RY, SEL_RZ) break;
        case 2u:  ACCUM_CASE(SEL_LZ, SEL_LW, SEL_RX, SEL_RY) break;
        default:  ACCUM_CASE(SEL_LY, SEL_LZ, SEL_LW, SEL_RX) break;
        }
    }

    // epilogue: out = 0.5*(vol + acc), each element written exactly once
    const size_t line = (((size_t)(b * C_DIM) * H_DIM + x) * H_DIM + y) * (H_DIM/4) + lane;
    const size_t cstр = (size_t)H_DIM * H_DIM * (H_DIM/4);
    #define EPI(C, ACC)                                                         \
        {                                                                       \
            size_t o = line + (size_t)(C) * cstр;                               \
            float4 v = __ldg(vol4 + o);                                         \
            float4 rr;                                                          \
            rr.x = (v.x + ACC.x) * 0.5f;                                        \
            rr.y = (v.y + ACC.y) * 0.5f;                                        \
            rr.z = (v.z + ACC.z) * 0.5f;                                        \
            rr.w = (v.w + ACC.w) * 0.5f;                                        \
            out4[o] = rr;                                                       \
        }
    EPI(0, acc0)
    EPI(1, acc1)
    EPI(2, acc2)
    EPI(3, acc3)
}

extern "C" void kernel_launch(void* const* d_in, const int* in_sizes, int n_in,
                              void* d_out, int out_size) {
    const float4* patches = (const float4*)d_in[0];
    const float4* vol     = (const float4*)d_in[1];
    const int*    centers = (const int*)d_in[2];
    float4*       out     = (float4*)d_out;

    // 32768 warps (2 batches x 128 x x 128 y), 8 warps per block -> 4096 blocks
    pi_fused_kernel<<<4096, 256>>>(patches, vol, centers, out);
}